// round 1
// baseline (speedup 1.0000x reference)
#include <cuda_runtime.h>
#include <cstdint>

// ---------------------------------------------------------------------------
// TensorNet interaction, restructured:
//   Insight: message passing gathers at dst AND segment-sums by dst, so
//   msg[n] = (component tensors of n) * (per-node scalar sums of edge MLP
//   outputs). Graph part reduces to a scatter-add of the 96 edge-MLP outputs
//   into acc[n][96].
//
// Kernel 1: zero acc
// Kernel 2: edge MLP (3-layer silu MLP, cosine cutoff) + vectorized
//           red.global.add.v4.f32 scatter into acc
// Kernel 3: per-node tensor math (warp per node, lane = unit)
// ---------------------------------------------------------------------------

#define MAXN 50000
#define PI_F 3.14159265358979323846f
#define CUTOFF_F 5.0f

__device__ float g_acc[(size_t)MAXN * 96];

__device__ __forceinline__ float silu_f(float v) {
    return v * __fdividef(1.0f, 1.0f + __expf(-v));
}

// ---------------------------------------------------------------------------
__global__ void zero_acc_kernel(int n4) {
    int i = blockIdx.x * blockDim.x + threadIdx.x;
    if (i < n4) reinterpret_cast<float4*>(g_acc)[i] = make_float4(0.f, 0.f, 0.f, 0.f);
}

// ---------------------------------------------------------------------------
// Edge MLP: thread per edge. Weights in SMEM, read in lockstep (broadcast).
__global__ void __launch_bounds__(128)
edge_mlp_kernel(const float* __restrict__ edge_attr,
                const int*   __restrict__ edge_index,
                const float* __restrict__ edge_weight,
                const float* __restrict__ W1, const float* __restrict__ b1,
                const float* __restrict__ W2, const float* __restrict__ b2,
                const float* __restrict__ W3, const float* __restrict__ b3,
                int E)
{
    __shared__ float sW1[1024];
    __shared__ float sW2[2048];
    __shared__ float sW3[6144];
    __shared__ float sB1[32], sB2[64], sB3[96];

    for (int i = threadIdx.x; i < 1024; i += 128) sW1[i] = W1[i];
    for (int i = threadIdx.x; i < 2048; i += 128) sW2[i] = W2[i];
    for (int i = threadIdx.x; i < 6144; i += 128) sW3[i] = W3[i];
    if (threadIdx.x < 32) sB1[threadIdx.x] = b1[threadIdx.x];
    if (threadIdx.x < 64) sB2[threadIdx.x] = b2[threadIdx.x];
    if (threadIdx.x < 96) sB3[threadIdx.x] = b3[threadIdx.x];
    __syncthreads();

    int e = blockIdx.x * 128 + threadIdx.x;
    if (e >= E) return;

    // load edge_attr row (32 floats, 128B line per thread)
    float x[32];
    const float4* xr = reinterpret_cast<const float4*>(edge_attr + (size_t)e * 32);
    #pragma unroll
    for (int q = 0; q < 8; q++) {
        float4 v = __ldg(xr + q);
        x[4*q+0] = v.x; x[4*q+1] = v.y; x[4*q+2] = v.z; x[4*q+3] = v.w;
    }

    float w = edge_weight[e];
    float Cc = (w < CUTOFF_F) ? 0.5f * (__cosf(w * (PI_F / CUTOFF_F)) + 1.0f) : 0.0f;
    int dst = edge_index[E + e];   // edge_index shape (2,E): row 1 = dst

    // Layer 1: 32 -> 32
    float h1[32];
    #pragma unroll
    for (int o = 0; o < 32; o++) {
        float a = sB1[o];
        const float4* wr = reinterpret_cast<const float4*>(sW1 + o * 32);
        #pragma unroll
        for (int q = 0; q < 8; q++) {
            float4 wv = wr[q];
            a += wv.x * x[4*q] + wv.y * x[4*q+1] + wv.z * x[4*q+2] + wv.w * x[4*q+3];
        }
        h1[o] = silu_f(a);
    }

    // Layer 2: 32 -> 64
    float h2[64];
    #pragma unroll
    for (int o = 0; o < 64; o++) {
        float a = sB2[o];
        const float4* wr = reinterpret_cast<const float4*>(sW2 + o * 32);
        #pragma unroll
        for (int q = 0; q < 8; q++) {
            float4 wv = wr[q];
            a += wv.x * h1[4*q] + wv.y * h1[4*q+1] + wv.z * h1[4*q+2] + wv.w * h1[4*q+3];
        }
        h2[o] = silu_f(a);
    }

    // Layer 3: 64 -> 96, streamed in chunks of 4 -> vector scatter-add
    float* nodeacc = g_acc + (size_t)dst * 96;
    #pragma unroll 1
    for (int og = 0; og < 24; og++) {
        float t[4];
        #pragma unroll
        for (int oo = 0; oo < 4; oo++) {
            int o = og * 4 + oo;
            float a = sB3[o];
            const float4* wr = reinterpret_cast<const float4*>(sW3 + o * 64);
            #pragma unroll
            for (int q = 0; q < 16; q++) {
                float4 wv = wr[q];
                a += wv.x * h2[4*q] + wv.y * h2[4*q+1] + wv.z * h2[4*q+2] + wv.w * h2[4*q+3];
            }
            t[oo] = silu_f(a) * Cc;
        }
        asm volatile("red.global.add.v4.f32 [%0], {%1, %2, %3, %4};"
                     :: "l"(nodeacc + og * 4),
                        "f"(t[0]), "f"(t[1]), "f"(t[2]), "f"(t[3])
                     : "memory");
    }
}

// ---------------------------------------------------------------------------
// Node kernel: one warp per node, lane = unit (U=32).
#define NODE_WARPS 8
__global__ void __launch_bounds__(32 * NODE_WARPS)
node_kernel(const float* __restrict__ X,
            const float* __restrict__ Wt,
            float* __restrict__ out,
            int nNodes)
{
    // sWt[c][k][m] = Wt[c][m][k]  (transposed so lane m reads consecutive)
    __shared__ float sWt[6][32][32];
    __shared__ float vst[NODE_WARPS][32][12];   // staged components, padded to 12

    for (int i = threadIdx.x; i < 6144; i += 32 * NODE_WARPS) {
        int c = i >> 10, r = i & 1023;
        int m = r >> 5, k = r & 31;
        sWt[c][k][m] = Wt[i];
    }
    __syncthreads();

    int warpId = threadIdx.x >> 5;
    int lane   = threadIdx.x & 31;
    float (*vp)[12] = vst[warpId];

    for (int n = blockIdx.x * NODE_WARPS + warpId; n < nNodes;
         n += gridDim.x * NODE_WARPS) {

        // ---- load X[n,:,:,lane], normalize ----
        float Xn[9];
        float nrm = 1.0f;
        #pragma unroll
        for (int t = 0; t < 9; t++) {
            float v = X[((size_t)n * 9 + t) * 32 + lane];
            Xn[t] = v; nrm += v * v;
        }
        float inv = __fdividef(1.0f, nrm);
        #pragma unroll
        for (int t = 0; t < 9; t++) Xn[t] *= inv;

        // ---- decompose Xn -> 9 independent components ----
        // c0 = trace/3; c1..c3 = antisym (01,02,12); c4..c8 = sym traceless
        // (s00,s01,s02,s11,s12); s22 derived.
        float tr3 = (Xn[0] + Xn[4] + Xn[8]) * (1.0f / 3.0f);
        float c[9];
        c[0] = tr3;
        c[1] = 0.5f * (Xn[1] - Xn[3]);
        c[2] = 0.5f * (Xn[2] - Xn[6]);
        c[3] = 0.5f * (Xn[5] - Xn[7]);
        c[4] = Xn[0] - tr3;
        c[5] = 0.5f * (Xn[1] + Xn[3]);
        c[6] = 0.5f * (Xn[2] + Xn[6]);
        c[7] = Xn[4] - tr3;
        c[8] = 0.5f * (Xn[5] + Xn[7]);

        // ---- stage 1 unit mixing: r[m] = sum_k c[k] * Wt[0/1/2][m,k] ----
        __syncwarp();
        #pragma unroll
        for (int t = 0; t < 9; t++) vp[lane][t] = c[t];
        __syncwarp();

        float r[9] = {0,0,0,0,0,0,0,0,0};
        #pragma unroll 8
        for (int k = 0; k < 32; k++) {
            const float4* q4 = reinterpret_cast<const float4*>(&vp[k][0]);
            float4 p0 = q4[0], p1 = q4[1];
            float v8 = vp[k][8];
            float wI = sWt[0][k][lane];
            float wA = sWt[1][k][lane];
            float wS = sWt[2][k][lane];
            r[0] += wI * p0.x;
            r[1] += wA * p0.y; r[2] += wA * p0.z; r[3] += wA * p0.w;
            r[4] += wS * p1.x; r[5] += wS * p1.y; r[6] += wS * p1.z;
            r[7] += wS * p1.w; r[8] += wS * v8;
        }

        float Ip = r[0], a01 = r[1], a02 = r[2], a12 = r[3];
        float s00 = r[4], s01 = r[5], s02 = r[6], s11 = r[7], s12 = r[8];
        float s22 = -(s00 + s11);

        // ---- per-node edge sums (acc indexed by output unit) ----
        const float* ap = g_acc + (size_t)n * 96 + lane * 3;
        float sI = ap[0], sA = ap[1], sS = ap[2];

        // ---- Y = I'+A'+S', msg G = I'*sI + A'*sA + S'*sS ----
        float Y[9], G[9];
        Y[0] = Ip + s00;  Y[1] = a01 + s01;  Y[2] = a02 + s02;
        Y[3] = s01 - a01; Y[4] = Ip + s11;   Y[5] = a12 + s12;
        Y[6] = s02 - a02; Y[7] = s12 - a12;  Y[8] = Ip + s22;
        G[0] = Ip*sI + s00*sS;  G[1] = a01*sA + s01*sS;  G[2] = a02*sA + s02*sS;
        G[3] = s01*sS - a01*sA; G[4] = Ip*sI + s11*sS;   G[5] = a12*sA + s12*sS;
        G[6] = s02*sS - a02*sA; G[7] = s12*sS - a12*sA;  G[8] = Ip*sI + s22*sS;

        // ---- M = Y@G + G@Y ----
        float M[9];
        #pragma unroll
        for (int i = 0; i < 3; i++)
            #pragma unroll
            for (int l = 0; l < 3; l++) {
                float a2 = 0.0f;
                #pragma unroll
                for (int j = 0; j < 3; j++)
                    a2 += Y[i*3+j] * G[j*3+l] + G[i*3+j] * Y[j*3+l];
                M[i*3+l] = a2;
            }

        // ---- decompose M, scale by 1/(|M|^2+1) ----
        float np = 1.0f;
        #pragma unroll
        for (int t = 0; t < 9; t++) np += M[t] * M[t];
        float inv2 = __fdividef(1.0f, np);
        float trm = (M[0] + M[4] + M[8]) * (1.0f / 3.0f);
        c[0] = trm * inv2;
        c[1] = 0.5f * (M[1] - M[3]) * inv2;
        c[2] = 0.5f * (M[2] - M[6]) * inv2;
        c[3] = 0.5f * (M[5] - M[7]) * inv2;
        c[4] = (M[0] - trm) * inv2;
        c[5] = 0.5f * (M[1] + M[3]) * inv2;
        c[6] = 0.5f * (M[2] + M[6]) * inv2;
        c[7] = (M[4] - trm) * inv2;
        c[8] = 0.5f * (M[5] + M[7]) * inv2;

        // ---- stage 2 unit mixing with Wt[3/4/5] ----
        __syncwarp();
        #pragma unroll
        for (int t = 0; t < 9; t++) vp[lane][t] = c[t];
        __syncwarp();

        float r2[9] = {0,0,0,0,0,0,0,0,0};
        #pragma unroll 8
        for (int k = 0; k < 32; k++) {
            const float4* q4 = reinterpret_cast<const float4*>(&vp[k][0]);
            float4 p0 = q4[0], p1 = q4[1];
            float v8 = vp[k][8];
            float wI = sWt[3][k][lane];
            float wA = sWt[4][k][lane];
            float wS = sWt[5][k][lane];
            r2[0] += wI * p0.x;
            r2[1] += wA * p0.y; r2[2] += wA * p0.z; r2[3] += wA * p0.w;
            r2[4] += wS * p1.x; r2[5] += wS * p1.y; r2[6] += wS * p1.z;
            r2[7] += wS * p1.w; r2[8] += wS * v8;
        }
        __syncwarp();

        float Ip2 = r2[0], b01 = r2[1], b02 = r2[2], b12 = r2[3];
        float t00 = r2[4], t01 = r2[5], t02 = r2[6], t11 = r2[7], t12 = r2[8];
        float t22 = -(t00 + t11);

        float D[9];
        D[0] = Ip2 + t00;  D[1] = b01 + t01;  D[2] = b02 + t02;
        D[3] = t01 - b01;  D[4] = Ip2 + t11;  D[5] = b12 + t12;
        D[6] = t02 - b02;  D[7] = t12 - b12;  D[8] = Ip2 + t22;

        // ---- out = Xn + dX + dX @ dX ----
        #pragma unroll
        for (int i = 0; i < 3; i++)
            #pragma unroll
            for (int l = 0; l < 3; l++) {
                float o = Xn[i*3+l] + D[i*3+l];
                #pragma unroll
                for (int j = 0; j < 3; j++)
                    o += D[i*3+j] * D[j*3+l];
                out[((size_t)n * 9 + (i*3+l)) * 32 + lane] = o;
            }
    }
}

// ---------------------------------------------------------------------------
extern "C" void kernel_launch(void* const* d_in, const int* in_sizes, int n_in,
                              void* d_out, int out_size)
{
    const float* X           = (const float*)d_in[0];
    const int*   edge_index  = (const int*)  d_in[1];
    const float* edge_weight = (const float*)d_in[2];
    const float* edge_attr   = (const float*)d_in[3];
    const float* W1 = (const float*)d_in[4];
    const float* b1 = (const float*)d_in[5];
    const float* W2 = (const float*)d_in[6];
    const float* b2 = (const float*)d_in[7];
    const float* W3 = (const float*)d_in[8];
    const float* b3 = (const float*)d_in[9];
    const float* Wt = (const float*)d_in[10];
    float* out = (float*)d_out;

    int N = in_sizes[0] / 288;   // X is (N,3,3,32)
    if (N > MAXN) N = MAXN;
    int E = in_sizes[2];         // edge_weight is (E,)

    int n4 = N * 24;             // N*96 floats as float4
    zero_acc_kernel<<<(n4 + 255) / 256, 256>>>(n4);

    edge_mlp_kernel<<<(E + 127) / 128, 128>>>(
        edge_attr, edge_index, edge_weight, W1, b1, W2, b2, W3, b3, E);

    node_kernel<<<(N + NODE_WARPS - 1) / NODE_WARPS, 32 * NODE_WARPS>>>(
        X, Wt, out, N);
}